// round 17
// baseline (speedup 1.0000x reference)
#include <cuda_runtime.h>
#include <cuda_bf16.h>
#include <cstdint>

// LinearMimo heterogeneous split, ONE launch:
//   batches 0-15  -> tensor-core FIR-GEMM blocks (mma.sync, bf16 2-way split)
//   batches 16-31 -> scalar-FFMA chunked IIR blocks (R8 structure)
// The two paths stress nearly disjoint SM resources (tensor+LDSM vs fma pipe),
// so they overlap; each path does half its standalone work.
// grid (97, 16): bx 0..63 GEMM (2 tiles each, b=by); bx==64 exact-head (b=by);
// bx 65..96 FFMA blocks (sup=bx-65, b=16+by).
// R15 crash fix: spool was sized 1200 floats; FFMA path needs 4*1200=4800.

#define Bb 32
#define Tt 16384
#define NT 16            // FIR taps
#define NS 8             // tap-pairs = K16 MMA steps
#define AROWS 144        // 143 rows used: u[t0-15 .. t0+127]

// ---- FFMA path constants (R8-verified) ----
#define FLc 128
#define FWm 16
#define FSLOTS 146       // slot r <-> t = cg*FLc - 18 + r
#define FCH 4
#define FPLANE 300
#define FCHUNK (4 * FPLANE)   // 1200 floats/chunk

#define SPOOL_FLOATS (FCH * FCHUNK)   // 4800 floats = 19.2 KB (max of 3 users)

static __device__ __forceinline__ uint32_t smem_u32(const void* p) {
    uint32_t a;
    asm("{.reg .u64 t; cvta.to.shared.u64 t, %1; cvt.u32.u64 %0, t;}" : "=r"(a) : "l"(p));
    return a;
}

#define MMA16816(C, A0, A1, A2, A3, B0, B1)                                  \
    asm volatile(                                                            \
        "mma.sync.aligned.m16n8k16.row.col.f32.bf16.bf16.f32 "               \
        "{%0,%1,%2,%3}, {%4,%5,%6,%7}, {%8,%9}, {%0,%1,%2,%3};"              \
        : "+f"((C)[0]), "+f"((C)[1]), "+f"((C)[2]), "+f"((C)[3])             \
        : "r"(A0), "r"(A1), "r"(A2), "r"(A3), "r"(B0), "r"(B1));

#define LDSM4(R0, R1, R2, R3, ADDR)                                          \
    asm volatile("ldmatrix.sync.aligned.m8n8.x4.shared.b16 {%0,%1,%2,%3}, [%4];" \
                 : "=r"(R0), "=r"(R1), "=r"(R2), "=r"(R3) : "r"(ADDR));

#define STEP2S(UA, UB, PS)                                                   \
    {                                                                        \
        float firA_ = fmaf(cb2x, u2x, fmaf(cb1x, u1x, cb0x * (UA)));         \
        float xnA_ = fmaf(na0x, x1x, fmaf(na1x, x2x, firA_));                \
        x2x = x1x; x1x = xnA_; u2x = u1x; u1x = (UA);                        \
        float firB_ = fmaf(cb2y, u2y, fmaf(cb1y, u1y, cb0y * (UB)));         \
        float xnB_ = fmaf(na0y, x1y, fmaf(na1y, x2y, firB_));                \
        x2y = x1y; x1y = xnB_; u2y = u1y; u1y = (UB);                        \
        PS = xnA_ + xnB_;                                                    \
    }
#define STEP2N(UA, UB)                                                       \
    {                                                                        \
        float firA_ = fmaf(cb2x, u2x, fmaf(cb1x, u1x, cb0x * (UA)));         \
        float xnA_ = fmaf(na0x, x1x, fmaf(na1x, x2x, firA_));                \
        x2x = x1x; x1x = xnA_; u2x = u1x; u1x = (UA);                        \
        float firB_ = fmaf(cb2y, u2y, fmaf(cb1y, u1y, cb0y * (UB)));         \
        float xnB_ = fmaf(na0y, x1y, fmaf(na1y, x2y, firB_));                \
        x2y = x1y; x1y = xnB_; u2y = u1y; u1y = (UB);                        \
    }

struct __align__(16) FSmem {
    __nv_bfloat16 ahi[AROWS * 8];
    __nv_bfloat16 alo[AROWS * 8];
};

// warp-level i-sum + coalesced store for the scalar paths
#define REDUCE_STORE(PS0, PS1, PS2, PS3, YP, SOFF)                           \
    {                                                                        \
        const float sA0 = hi1 ? (PS0) : (PS2);                               \
        const float sA1 = hi1 ? (PS1) : (PS3);                               \
        const float rA0 = __shfl_xor_sync(0xffffffffu, sA0, 16);             \
        const float rA1 = __shfl_xor_sync(0xffffffffu, sA1, 16);             \
        const float w0 = (hi1 ? (PS2) : (PS0)) + rA0;                        \
        const float w1 = (hi1 ? (PS3) : (PS1)) + rA1;                        \
        const float sB = hi0 ? w0 : w1;                                      \
        const float rB = __shfl_xor_sync(0xffffffffu, sB, 8);                \
        const float mine = hi0 ? w1 : w0;                                    \
        (YP)[(size_t)((SOFF) + iq) * 8] = mine + rB;                         \
    }

__global__ void __launch_bounds__(128) hetero_kernel(
    const float* __restrict__ bc, const float* __restrict__ ac,
    const float* __restrict__ u_in, const float* __restrict__ y0,
    const float* __restrict__ u0, float* __restrict__ y)
{
    const int by = blockIdx.y;
    const int bx = blockIdx.x;
    const int tid = threadIdx.x;
    __shared__ __align__(16) float spool[SPOOL_FLOATS];   // 4800 floats, 19.2 KB

    // ===================== FFMA path: batches 16..31 =======================
    if (bx >= 65) {
        const int b = 16 + by;
        const int sup = bx - 65;             // 0..31
        const int o = tid & 7, iq = (tid >> 3) & 3, cb = tid >> 5;
        const int cg = sup * FCH + cb;
        float* us = spool;

        float cb0x, cb1x, cb2x, na0x, na1x, cb0y, cb1y, cb2y, na0y, na1y;
        {
            const float* bq = bc + o * 24 + iq * 6;
            cb0x = bq[0]; cb1x = bq[1]; cb2x = bq[2];
            cb0y = bq[3]; cb1y = bq[4]; cb2y = bq[5];
            const float4 av = *(const float4*)(ac + o * 16 + iq * 4);
            na0x = -av.x; na1x = -av.y; na0y = -av.z; na1y = -av.w;
        }
#pragma unroll
        for (int c = 0; c < FCH; c++) {
            const int cgl = sup * FCH + c;
            float* dst = us + c * FCHUNK;
            const int lo = (cgl == 0) ? 36 : 0;
            const float4* src = (const float4*)u_in +
                ((cgl == 0) ? (size_t)b * Tt * 2
                            : ((size_t)b * Tt + (size_t)cgl * FLc - 18) * 2) - lo;
#pragma unroll
            for (int k = 0; k < 3; k++) {
                const int j = k * 128 + tid;
                if (j >= lo && j < FSLOTS * 2) {
                    const float4 v = src[j];
                    const int ts = j >> 1, h = j & 1;
                    float* p0 = dst + (2 * h) * FPLANE + ts * 2;
                    float* p1 = p0 + FPLANE;
                    p0[0] = v.x; p0[1] = v.y; p1[0] = v.z; p1[1] = v.w;
                }
            }
        }
        if (sup == 0 && tid < 16) {
            const int r = 16 + (tid >> 3), ii = tid & 7;
            // u_0[...,k] = u[-1-k]: slot 17 -> u[-1] (k=0), slot 16 -> u[-2] (k=1)
            us[(ii >> 1) * FPLANE + r * 2 + (ii & 1)] = u0[(b * 8 + ii) * 3 + (17 - r)];
        }
        __syncthreads();

        const float* upq = us + cb * FCHUNK + iq * FPLANE;
        float x1x, x2x, u1x, u2x, x1y, x2y, u1y, u2y;
        if (cg == 0) {
            const float4 v = *(const float4*)(y0 + (b * 8 + o) * 16 + iq * 4);
            x1x = v.x; x2x = v.y; x1y = v.z; x2y = v.w;
            const float4 w = *(const float4*)(upq + 16 * 2);  // slots 16,17
            u2x = w.x; u2y = w.y; u1x = w.z; u1y = w.w;
        } else {
            x1x = x2x = x1y = x2y = 0.f;
            const float4 w = *(const float4*)(upq + 0);
            u2x = w.x; u2y = w.y; u1x = w.z; u1y = w.w;
#pragma unroll
            for (int r = 2; r < 2 + FWm; r += 2) {
                const float4 v = *(const float4*)(upq + r * 2);
                STEP2N(v.x, v.y) STEP2N(v.z, v.w)
            }
        }
        float* yp = y + ((size_t)b * Tt + (size_t)cg * FLc) * 8 + o;
        const bool hi1 = (iq & 2) != 0, hi0 = (iq & 1) != 0;
#pragma unroll 4
        for (int s = 0; s < FLc; s += 4) {
            float ps0, ps1, ps2, ps3;
            const float4 va = *(const float4*)(upq + (18 + s) * 2);
            STEP2S(va.x, va.y, ps0)
            STEP2S(va.z, va.w, ps1)
            const float4 vb = *(const float4*)(upq + (20 + s) * 2);
            STEP2S(vb.x, vb.y, ps2)
            STEP2S(vb.z, vb.w, ps3)
            REDUCE_STORE(ps0, ps1, ps2, ps3, yp, s)
        }
        return;
    }

    // ===================== exact-head block: batches 0..15 =================
    if (bx == 64) {
        const int b = by;
        const int o = tid & 7, iq = (tid >> 3) & 3, cb = tid >> 5;
        float* us = spool;   // 4 chunks x 4 planes x 104 = 1664 floats

        const float* bq = bc + o * 24 + iq * 6;
        const float cb0x = bq[0], cb1x = bq[1], cb2x = bq[2];
        const float cb0y = bq[3], cb1y = bq[4], cb2y = bq[5];
        const float4 av = *(const float4*)(ac + o * 16 + iq * 4);
        const float na0x = -av.x, na1x = -av.y, na0y = -av.z, na1y = -av.w;

        // tile: slot r <-> t = c*32 - 18 + r (50 slots per chunk)
#pragma unroll
        for (int c = 0; c < 4; c++) {
            float* dst = us + c * 416;
            const int lo = (c == 0) ? 36 : 0;
            const float4* src = (const float4*)u_in +
                ((c == 0) ? (size_t)b * Tt * 2 : ((size_t)b * Tt + c * 32 - 18) * 2) - lo;
            if (tid >= lo && tid < 100) {
                const float4 v = src[tid];
                const int ts = tid >> 1, h = tid & 1;
                float* p0 = dst + (2 * h) * 104 + ts * 2;
                p0[0] = v.x; p0[1] = v.y; p0[104] = v.z; p0[105] = v.w;
            }
        }
        if (tid < 16) {
            const int r = 16 + (tid >> 3), ii = tid & 7;
            us[(ii >> 1) * 104 + r * 2 + (ii & 1)] = u0[(b * 8 + ii) * 3 + (17 - r)];
        }
        __syncthreads();

        const float* upq = us + cb * 416 + iq * 104;
        float x1x, x2x, u1x, u2x, x1y, x2y, u1y, u2y;
        if (cb == 0) {
            const float4 v = *(const float4*)(y0 + (b * 8 + o) * 16 + iq * 4);
            x1x = v.x; x2x = v.y; x1y = v.z; x2y = v.w;
            const float4 w = *(const float4*)(upq + 16 * 2);
            u2x = w.x; u2y = w.y; u1x = w.z; u1y = w.w;
        } else {
            x1x = x2x = x1y = x2y = 0.f;
            const float4 w = *(const float4*)(upq);
            u2x = w.x; u2y = w.y; u1x = w.z; u1y = w.w;
#pragma unroll
            for (int r = 2; r < 18; r += 2) {
                const float4 v = *(const float4*)(upq + r * 2);
                STEP2N(v.x, v.y) STEP2N(v.z, v.w)
            }
        }
        float* yp = y + ((size_t)b * Tt + cb * 32) * 8 + o;
        const bool hi1 = (iq & 2) != 0, hi0 = (iq & 1) != 0;
#pragma unroll
        for (int s = 0; s < 32; s += 4) {
            float ps0, ps1, ps2, ps3;
            const float4 va = *(const float4*)(upq + (18 + s) * 2);
            STEP2S(va.x, va.y, ps0)
            STEP2S(va.z, va.w, ps1)
            const float4 vb = *(const float4*)(upq + (20 + s) * 2);
            STEP2S(vb.x, vb.y, ps2)
            STEP2S(vb.z, vb.w, ps3)
            REDUCE_STORE(ps0, ps1, ps2, ps3, yp, s)
        }
        return;
    }

    // ===================== GEMM blocks: batches 0..15 ======================
    {
        const int b = by;
        FSmem* sm = (FSmem*)spool;    // 1152 floats used of 4800
        const int wid = tid >> 5, lid = tid & 31;
        const int tc = lid & 3, g = lid >> 2;

        // B fragments in registers: lane (g,tc) runs its own two tap recurrences
        uint32_t bh0[NS], bh1[NS], bl0[NS], bl1[NS];
        {
            const int fA = g * 8 + 2 * tc, fB = fA + 1;
            const float bA0 = bc[fA * 3 + 0], bA1 = bc[fA * 3 + 1], bA2 = bc[fA * 3 + 2];
            const float bB0 = bc[fB * 3 + 0], bB1 = bc[fB * 3 + 1], bB2 = bc[fB * 3 + 2];
            const float2 aA = *(const float2*)(ac + fA * 2);
            const float2 aB = *(const float2*)(ac + fB * 2);
            float hA1 = 0.f, hA2 = 0.f, hB1 = 0.f, hB2 = 0.f;
#pragma unroll
            for (int d = 0; d < NT; d++) {
                const float fa = (d == 0) ? bA0 : (d == 1) ? bA1 : (d == 2) ? bA2 : 0.f;
                const float fb = (d == 0) ? bB0 : (d == 1) ? bB1 : (d == 2) ? bB2 : 0.f;
                const float hA = fa - aA.x * hA1 - aA.y * hA2;
                const float hB = fb - aB.x * hB1 - aB.y * hB2;
                hA2 = hA1; hA1 = hA; hB2 = hB1; hB1 = hB;
                const __nv_bfloat16 hiA = __float2bfloat16(hA);
                const __nv_bfloat16 hiB = __float2bfloat16(hB);
                __nv_bfloat162 hp = __halves2bfloat162(hiA, hiB);
                __nv_bfloat162 lp = __halves2bfloat162(
                    __float2bfloat16(hA - __bfloat162float(hiA)),
                    __float2bfloat16(hB - __bfloat162float(hiB)));
                if (d & 1) { bh0[d >> 1] = *(uint32_t*)&hp; bl0[d >> 1] = *(uint32_t*)&lp; }
                else       { bh1[d >> 1] = *(uint32_t*)&hp; bl1[d >> 1] = *(uint32_t*)&lp; }
            }
        }

        const uint32_t ahi_u = smem_u32(sm->ahi);
        const uint32_t alo_u = smem_u32(sm->alo);
        // ldmatrix lane address: lanes 0-15 -> rows 0-15 (k 0-7), 16-31 -> +1 row
        const uint32_t rowoff = (uint32_t)(((lid & 15) + (lid >> 4)) * 16);

#pragma unroll
        for (int k = 0; k < 2; k++) {
            const int t_idx = 1 + bx * 2 + k;       // 1..128; 128 masked
            const bool active = (t_idx <= 127);
            if (active) {
                const int t0 = t_idx * 128;
                const float4* src = (const float4*)u_in + ((size_t)b * Tt + t0 - 15) * 2;
                for (int q = tid; q < 143 * 2; q += 128) {
                    const float4 v = src[q];
                    const __nv_bfloat16 h0 = __float2bfloat16(v.x);
                    const __nv_bfloat16 h1 = __float2bfloat16(v.y);
                    const __nv_bfloat16 h2 = __float2bfloat16(v.z);
                    const __nv_bfloat16 h3 = __float2bfloat16(v.w);
                    const __nv_bfloat16 l0 = __float2bfloat16(v.x - __bfloat162float(h0));
                    const __nv_bfloat16 l1 = __float2bfloat16(v.y - __bfloat162float(h1));
                    const __nv_bfloat16 l2 = __float2bfloat16(v.z - __bfloat162float(h2));
                    const __nv_bfloat16 l3 = __float2bfloat16(v.w - __bfloat162float(h3));
                    __nv_bfloat162* dh = (__nv_bfloat162*)sm->ahi + q * 2;
                    dh[0] = __halves2bfloat162(h0, h1);
                    dh[1] = __halves2bfloat162(h2, h3);
                    __nv_bfloat162* dl = (__nv_bfloat162*)sm->alo + q * 2;
                    dl[0] = __halves2bfloat162(l0, l1);
                    dl[1] = __halves2bfloat162(l2, l3);
                }
            }
            __syncthreads();
            if (active) {
                float acc[2][4];
#pragma unroll
                for (int m = 0; m < 2; m++)
#pragma unroll
                    for (int e = 0; e < 4; e++) acc[m][e] = 0.f;
#pragma unroll
                for (int s = 0; s < NS; s++) {
#pragma unroll
                    for (int m = 0; m < 2; m++) {
                        const int mt = wid * 2 + m;
                        // A_s row t: k0-7 = u[t0+t-2s-1] -> smem row j = t+14-2s
                        const uint32_t base =
                            (uint32_t)((mt * 16 + 14 - 2 * s) * 16) + rowoff;
                        uint32_t ah0, ah1, ah2, ah3, al0r, al1r, al2r, al3r;
                        LDSM4(ah0, ah1, ah2, ah3, ahi_u + base)
                        LDSM4(al0r, al1r, al2r, al3r, alo_u + base)
                        MMA16816(acc[m], ah0, ah1, ah2, ah3, bh0[s], bh1[s])
                        MMA16816(acc[m], al0r, al1r, al2r, al3r, bh0[s], bh1[s])
                        MMA16816(acc[m], ah0, ah1, ah2, ah3, bl0[s], bl1[s])
                    }
                }
                const int t0 = t_idx * 128;
#pragma unroll
                for (int m = 0; m < 2; m++) {
                    const int mt = wid * 2 + m;
                    float* dst = y + ((size_t)b * Tt + t0 + mt * 16 + g) * 8 + 2 * tc;
                    *(float2*)dst = make_float2(acc[m][0], acc[m][1]);
                    *(float2*)(dst + 64) = make_float2(acc[m][2], acc[m][3]);
                }
            }
            __syncthreads();
        }
    }
}

extern "C" void kernel_launch(void* const* d_in, const int* in_sizes, int n_in,
                              void* d_out, int out_size) {
    const float* bc = (const float*)d_in[0];  // b_coeff (O,I,3)
    const float* ac = (const float*)d_in[1];  // a_coeff (O,I,2)
    const float* u  = (const float*)d_in[2];  // u_in    (B,T,I)
    const float* y0 = (const float*)d_in[3];  // y_0     (B,O,I,2)
    const float* u0 = (const float*)d_in[4];  // u_0     (B,I,3)
    float* y = (float*)d_out;                 // (B,T,O)

    hetero_kernel<<<dim3(97, 16), 128>>>(bc, ac, u, y0, u0, y);
}